// round 6
// baseline (speedup 1.0000x reference)
#include <cuda_runtime.h>
#include <math.h>

#define NTOT 2010
#define QD 8
#define LTW 10
#define DIN 80
#define NH 2000
#define MI 256
#define DO 16
#define NCHUNK 59
#define CHUNK 34
#define JITTERF 1.0e-4f
#define PACKED 32896   // 256*257/2

// ---------------- device scratch (static, no allocation) ----------------
__device__ float g_P[NH*DIN], g_R[NH*DIN], g_U[NH*DIN], g_W[NH*DIN];
__device__ float g_a1[NH], g_lc1[NH], g_h[NH];
__device__ float g_F[NH*MI];
__device__ float g_psi1T[MI*NH];
__device__ float g_Kuu[MI*MI];
__device__ float g_pd[MI*MI];
__device__ float g_part[NCHUNK*MI*MI];
__device__ float g_psi2[MI*MI];
__device__ float g_Lp[PACKED];
__device__ float g_dinvA[MI];
__device__ float g_tmp[MI*MI];
__device__ float g_AAT[MI*MI];
__device__ float g_G[MI*DO];
__device__ float g_H[MI*DO];

__constant__ int c_ta[10] = {0,0,0,0,1,1,1,2,2,3};
__constant__ int c_tb[10] = {0,1,2,3,1,2,3,2,3,3};

// ---------------- per-n preprocessing ----------------
__global__ void k_prep(const float* __restrict__ Xm, const float* __restrict__ Xv,
                       const float* __restrict__ ls) {
    int n = blockIdx.x, t = threadIdx.x;
    float4 v = make_float4(0.f, 0.f, 0.f, 0.f);
    if (t < DIN) {
        int l = t / QD, q = t - l * QD;
        float xm = Xm[(1 + n + l) * QD + q];
        float xv = Xv[(1 + n + l) * QD + q];
        float lsv = ls[t];
        float ls2 = lsv * lsv;
        float d1 = xv + ls2, d2 = 2.f * xv + ls2;
        float id1 = 1.f / d1, id2 = 1.f / d2;
        g_P[n*DIN + t] = xm * id1;
        g_R[n*DIN + t] = id1;
        g_U[n*DIN + t] = xm * id2;
        g_W[n*DIN + t] = id2;
        v.x = xm * xm * id1;
        v.y = log1pf(xv / ls2);
        v.z = xm * xm * id2;
        v.w = log1pf(2.f * xv / ls2);
    }
    __shared__ float4 sr[128];
    sr[t] = v;
    __syncthreads();
    for (int s = 64; s > 0; s >>= 1) {
        if (t < s) {
            float4 a = sr[t], b = sr[t + s];
            a.x += b.x; a.y += b.y; a.z += b.z; a.w += b.w;
            sr[t] = a;
        }
        __syncthreads();
    }
    if (t == 0) {
        float4 r = sr[0];
        g_a1[n]  = r.x;
        g_lc1[n] = -0.5f * r.y;
        g_h[n]   = -0.5f * r.w - r.z;
    }
}

// ---------------- Kuu + kv^2*distfac ----------------
__global__ void k_kuu(const float* __restrict__ Z, const float* __restrict__ ls,
                      const float* __restrict__ kvp) {
    __shared__ float sZa[16][DIN+1], sZb[16][DIN+1], sil[DIN];
    int a0 = blockIdx.y * 16, b0 = blockIdx.x * 16;
    int tx = threadIdx.x, ty = threadIdx.y, tid = ty * 16 + tx;
    for (int i = tid; i < 16 * DIN; i += 256) {
        int r = i / DIN, q = i - r * DIN;
        sZa[r][q] = Z[(a0 + r) * DIN + q];
        sZb[r][q] = Z[(b0 + r) * DIN + q];
    }
    if (tid < DIN) { float L = ls[tid]; sil[tid] = 1.f / (L * L); }
    __syncthreads();
    float d2 = 0.f;
    #pragma unroll 16
    for (int q = 0; q < DIN; q++) {
        float d = sZa[ty][q] - sZb[tx][q];
        d2 = fmaf(d * d, sil[q], d2);
    }
    float kv = *kvp;
    int a = a0 + ty, b = b0 + tx;
    g_Kuu[a*MI + b] = kv * __expf(-0.5f * d2) + ((a == b) ? JITTERF : 0.f);
    g_pd[a*MI + b]  = kv * kv * __expf(-0.25f * d2);
}

// ---------------- psi1^T and F : 16n x 64m tiles ----------------
__global__ void __launch_bounds__(256) k_psi1F(const float* __restrict__ Z,
                                               const float* __restrict__ kvp) {
    __shared__ float sZm[DIN*64];        // [q][m]
    __shared__ float4 sS4[16*DIN];       // (P,R,U,W) per [n][q]
    int m0 = blockIdx.x * 64, n0 = blockIdx.y * 16;
    int tid = threadIdx.x;
    int mg = tid & 15, ny = tid >> 4;    // m-group (4 m's), n index
    for (int i = tid; i < 64 * DIN; i += 256) {
        int r = i & 63, q = i >> 6;
        sZm[q*64 + r] = Z[(m0 + r) * DIN + q];
    }
    for (int i = tid; i < 16 * DIN; i += 256) {
        int r = i / DIN, q = i - r * DIN;
        int ni = (n0 + r) * DIN + q;
        sS4[i] = make_float4(g_P[ni], g_R[ni], g_U[ni], g_W[ni]);
    }
    __syncthreads();
    float pz[4] = {}, rz[4] = {}, uz[4] = {}, wz[4] = {};
    #pragma unroll 5
    for (int q = 0; q < DIN; q++) {
        float4 z4 = *(const float4*)&sZm[q*64 + mg*4];
        float4 pw = sS4[ny*DIN + q];
        float z, zq;
        z = z4.x; zq = z*z;
        pz[0] = fmaf(pw.x, z, pz[0]); rz[0] = fmaf(pw.y, zq, rz[0]);
        uz[0] = fmaf(pw.z, z, uz[0]); wz[0] = fmaf(pw.w, zq, wz[0]);
        z = z4.y; zq = z*z;
        pz[1] = fmaf(pw.x, z, pz[1]); rz[1] = fmaf(pw.y, zq, rz[1]);
        uz[1] = fmaf(pw.z, z, uz[1]); wz[1] = fmaf(pw.w, zq, wz[1]);
        z = z4.z; zq = z*z;
        pz[2] = fmaf(pw.x, z, pz[2]); rz[2] = fmaf(pw.y, zq, rz[2]);
        uz[2] = fmaf(pw.z, z, uz[2]); wz[2] = fmaf(pw.w, zq, wz[2]);
        z = z4.w; zq = z*z;
        pz[3] = fmaf(pw.x, z, pz[3]); rz[3] = fmaf(pw.y, zq, rz[3]);
        uz[3] = fmaf(pw.z, z, uz[3]); wz[3] = fmaf(pw.w, zq, wz[3]);
    }
    int n = n0 + ny;
    float a1 = g_a1[n], lc1 = g_lc1[n], h = g_h[n];
    float kv = *kvp;
    #pragma unroll
    for (int k = 0; k < 4; k++) {
        int m = m0 + mg * 4 + k;
        g_psi1T[m*NH + n] = kv * __expf(fmaf(-0.5f, a1 - 2.f * pz[k] + rz[k], lc1));
        g_F[n*MI + m]     = __expf(0.5f * h + uz[k] - 0.25f * wz[k]);
    }
}

// ---------------- big psi2 kernel: n-pairs, exp2 domain ----------------
__global__ void __launch_bounds__(256, 2) k_psi2(const float* __restrict__ Z) {
    extern __shared__ float dsm[];
    float* sZa  = dsm;                 // DIN*64
    float* sZb  = sZa + DIN*64;
    float* sWZ0 = sZb + DIN*64;
    float* sWZ1 = sWZ0 + DIN*64;
    float* sS   = sWZ1 + DIN*64;       // 416 staging: W0(80) W1(80) Fa0 Fb0 Fa1 Fb1 (64 ea)
    float* sW0 = sS,        *sW1 = sS + 80;
    float* sFa0 = sS + 160, *sFb0 = sS + 224;
    float* sFa1 = sS + 288, *sFb1 = sS + 352;
    const float NHL2E = -0.7213475204444817f;  // -0.5*log2(e)
    int tp = blockIdx.x, ch = blockIdx.y;
    int a0 = c_ta[tp] * 64, b0 = c_tb[tp] * 64;
    int tid = threadIdx.x;
    for (int i = tid; i < 64 * DIN; i += 256) {
        int r = i & 63, q = i >> 6;
        sZa[q*64 + r] = Z[(a0 + r) * DIN + q];
        sZb[q*64 + r] = Z[(b0 + r) * DIN + q];
    }
    int tx = tid & 15, ty = tid >> 4;
    float acc[4][4] = {};
    int n0 = ch * CHUNK;
    int n1 = n0 + CHUNK; if (n1 > NH) n1 = NH;
    for (int n = n0; n + 1 < n1 + 1 && n + 1 <= n1; n += 2) {
        if (n + 1 >= n1 + 1) break;
        __syncthreads();
        for (int i = tid; i < 416; i += 256) {
            float v;
            if      (i < 80)  v = g_W[n*DIN + i];
            else if (i < 160) v = g_W[(n+1)*DIN + (i-80)];
            else if (i < 224) v = g_F[n*MI + a0 + (i-160)];
            else if (i < 288) v = g_F[n*MI + b0 + (i-224)];
            else if (i < 352) v = g_F[(n+1)*MI + a0 + (i-288)];
            else              v = g_F[(n+1)*MI + b0 + (i-352)];
            sS[i] = v;
        }
        __syncthreads();
        for (int i = tid; i < 64 * DIN; i += 256) {
            float za = sZa[i];
            int q = i >> 6;
            sWZ0[i] = NHL2E * sW0[q] * za;
            sWZ1[i] = NHL2E * sW1[q] * za;
        }
        __syncthreads();
        float C0[4][4] = {}, C1[4][4] = {};
        #pragma unroll 5
        for (int q = 0; q < DIN; q++) {
            float4 zb  = *(const float4*)&sZb[q*64 + ty*4];
            float4 wa0 = *(const float4*)&sWZ0[q*64 + tx*4];
            float4 wa1 = *(const float4*)&sWZ1[q*64 + tx*4];
            C0[0][0] = fmaf(wa0.x, zb.x, C0[0][0]); C0[0][1] = fmaf(wa0.x, zb.y, C0[0][1]);
            C0[0][2] = fmaf(wa0.x, zb.z, C0[0][2]); C0[0][3] = fmaf(wa0.x, zb.w, C0[0][3]);
            C0[1][0] = fmaf(wa0.y, zb.x, C0[1][0]); C0[1][1] = fmaf(wa0.y, zb.y, C0[1][1]);
            C0[1][2] = fmaf(wa0.y, zb.z, C0[1][2]); C0[1][3] = fmaf(wa0.y, zb.w, C0[1][3]);
            C0[2][0] = fmaf(wa0.z, zb.x, C0[2][0]); C0[2][1] = fmaf(wa0.z, zb.y, C0[2][1]);
            C0[2][2] = fmaf(wa0.z, zb.z, C0[2][2]); C0[2][3] = fmaf(wa0.z, zb.w, C0[2][3]);
            C0[3][0] = fmaf(wa0.w, zb.x, C0[3][0]); C0[3][1] = fmaf(wa0.w, zb.y, C0[3][1]);
            C0[3][2] = fmaf(wa0.w, zb.z, C0[3][2]); C0[3][3] = fmaf(wa0.w, zb.w, C0[3][3]);
            C1[0][0] = fmaf(wa1.x, zb.x, C1[0][0]); C1[0][1] = fmaf(wa1.x, zb.y, C1[0][1]);
            C1[0][2] = fmaf(wa1.x, zb.z, C1[0][2]); C1[0][3] = fmaf(wa1.x, zb.w, C1[0][3]);
            C1[1][0] = fmaf(wa1.y, zb.x, C1[1][0]); C1[1][1] = fmaf(wa1.y, zb.y, C1[1][1]);
            C1[1][2] = fmaf(wa1.y, zb.z, C1[1][2]); C1[1][3] = fmaf(wa1.y, zb.w, C1[1][3]);
            C1[2][0] = fmaf(wa1.z, zb.x, C1[2][0]); C1[2][1] = fmaf(wa1.z, zb.y, C1[2][1]);
            C1[2][2] = fmaf(wa1.z, zb.z, C1[2][2]); C1[2][3] = fmaf(wa1.z, zb.w, C1[2][3]);
            C1[3][0] = fmaf(wa1.w, zb.x, C1[3][0]); C1[3][1] = fmaf(wa1.w, zb.y, C1[3][1]);
            C1[3][2] = fmaf(wa1.w, zb.z, C1[3][2]); C1[3][3] = fmaf(wa1.w, zb.w, C1[3][3]);
        }
        float fa0[4], fb0[4], fa1[4], fb1[4];
        #pragma unroll
        for (int i = 0; i < 4; i++) {
            fa0[i] = sFa0[tx*4 + i]; fb0[i] = sFb0[ty*4 + i];
            fa1[i] = sFa1[tx*4 + i]; fb1[i] = sFb1[ty*4 + i];
        }
        #pragma unroll
        for (int i = 0; i < 4; i++)
            #pragma unroll
            for (int j = 0; j < 4; j++) {
                acc[i][j] = fmaf(fa0[i] * fb0[j], exp2f(C0[i][j]), acc[i][j]);
                acc[i][j] = fmaf(fa1[i] * fb1[j], exp2f(C1[i][j]), acc[i][j]);
            }
    }
    float* part = &g_part[(size_t)ch * MI * MI];
    #pragma unroll
    for (int i = 0; i < 4; i++) {
        int a = a0 + tx * 4 + i;
        #pragma unroll
        for (int j = 0; j < 4; j++) {
            int b = b0 + ty * 4 + j;
            part[a*MI + b] = acc[i][j];
        }
    }
}

// deterministic chunk reduction + symmetrization + pd scaling
__global__ void k_reduce_psi2() {
    int a = blockIdx.x, b = threadIdx.x;
    int ta = a >> 6, tb = b >> 6;
    if (ta > tb) return;
    int idx = a * MI + b;
    float s = 0.f;
    #pragma unroll
    for (int ch = 0; ch < NCHUNK; ch++) s += g_part[ch * MI * MI + idx];
    float v = g_pd[idx] * s;
    g_psi2[idx] = v;
    if (ta < tb) g_psi2[b * MI + a] = v;
}

// ============ shared Cholesky body ============
__device__ __forceinline__ void chol_body(float* sL, float* sD, float* sdi, int tid) {
    int lane = tid & 31, wid = tid >> 5;
    for (int K = 0; K < 4; K++) {
        int base = K * 64;
        for (int i = tid; i < 64 * 64; i += 1024) {
            int r = i >> 6, c = i & 63;
            if (c <= r) sD[r*65 + c] = sL[(((base+r)*(base+r+1))>>1) + base + c];
        }
        __syncthreads();
        if (wid == 0) {
            for (int k = 0; k < 64; k++) {
                if (lane == 0) {
                    float d = sqrtf(sD[k*65 + k]);
                    sD[k*65 + k] = d;
                    sdi[base + k] = 1.f / d;
                }
                __syncwarp();
                float inv = sdi[base + k];
                int r1 = lane + 32;
                if (lane > k) sD[lane*65 + k] *= inv;
                if (r1 > k)   sD[r1*65 + k]   *= inv;
                __syncwarp();
                float l0 = (lane > k) ? sD[lane*65 + k] : 0.f;
                float l1 = (r1 > k)   ? sD[r1*65 + k]   : 0.f;
                for (int j = k + 1; j <= lane; j++) sD[lane*65 + j] -= l0 * sD[j*65 + k];
                if (r1 > k)
                    for (int j = k + 1; j <= r1; j++) sD[r1*65 + j] -= l1 * sD[j*65 + k];
                __syncwarp();
            }
        }
        __syncthreads();
        for (int i = tid; i < 64 * 64; i += 1024) {
            int r = i >> 6, c = i & 63;
            if (c <= r) sL[(((base+r)*(base+r+1))>>1) + base + c] = sD[r*65 + c];
        }
        __syncthreads();
        int R = MI - base - 64;
        if (R > 0) {
            for (int rr = wid; rr < R; rr += 32) {
                int row = base + 64 + rr;
                int Pr = (row * (row + 1)) >> 1;
                float x0 = sL[Pr + base + lane];
                float x1 = sL[Pr + base + 32 + lane];
                #pragma unroll
                for (int m = 0; m < 64; m++) {
                    float src = (m < 32) ? x0 : x1;
                    float v = __shfl_sync(0xffffffffu, src, m & 31);
                    float xm = v * sdi[base + m];
                    if (m < 32) {
                        if (lane == m) x0 = xm;
                        if (lane > m)  x0 -= xm * sD[lane*65 + m];
                        x1 -= xm * sD[(lane+32)*65 + m];
                    } else {
                        if (lane == m - 32) x1 = xm;
                        if (lane + 32 > m)  x1 -= xm * sD[(lane+32)*65 + m];
                    }
                }
                sL[Pr + base + lane]      = x0;
                sL[Pr + base + 32 + lane] = x1;
            }
            __syncthreads();
            int T = R >> 5;
            int ntiles = (T * (T + 1)) >> 1;
            int g = tid >> 6, gt = tid & 63;
            int txx = gt & 7, tyy = gt >> 3;
            for (int tile = g; tile < ntiles; tile += 16) {
                int ti = 0, rem = tile;
                while (rem > ti) { rem -= (ti + 1); ti++; }
                int tj = rem;
                int gr = base + 64 + ti * 32, gc = base + 64 + tj * 32;
                int Pr[4], Pc[4];
                #pragma unroll
                for (int i = 0; i < 4; i++) { int r = gr + tyy*4 + i; Pr[i] = ((r*(r+1))>>1) + base; }
                #pragma unroll
                for (int j = 0; j < 4; j++) { int c = gc + txx*4 + j; Pc[j] = ((c*(c+1))>>1) + base; }
                float acc[4][4] = {};
                #pragma unroll 16
                for (int k = 0; k < 64; k++) {
                    float la[4], lb[4];
                    #pragma unroll
                    for (int i = 0; i < 4; i++) la[i] = sL[Pr[i] + k];
                    #pragma unroll
                    for (int j = 0; j < 4; j++) lb[j] = sL[Pc[j] + k];
                    #pragma unroll
                    for (int i = 0; i < 4; i++)
                        #pragma unroll
                        for (int j = 0; j < 4; j++)
                            acc[i][j] = fmaf(la[i], lb[j], acc[i][j]);
                }
                #pragma unroll
                for (int i = 0; i < 4; i++) {
                    int r = gr + tyy*4 + i;
                    int Prow = (r * (r + 1)) >> 1;
                    #pragma unroll
                    for (int j = 0; j < 4; j++) {
                        int c = gc + txx*4 + j;
                        if (c <= r) sL[Prow + c] -= acc[i][j];
                    }
                }
            }
        }
        __syncthreads();
    }
}

// chol(Kuu) -> packed L in global + dinv
__global__ void __launch_bounds__(1024) k_chol256(const float* __restrict__ A,
                                                  float* __restrict__ Lp,
                                                  float* __restrict__ dinv) {
    extern __shared__ float sm[];
    float* sL  = sm;
    float* sD  = sm + PACKED;
    float* sdi = sD + 64*65;
    int tid = threadIdx.x;
    {
        int r = tid >> 2, sub = tid & 3;
        int Pr = (r * (r + 1)) >> 1;
        for (int c = sub; c <= r; c += 4) sL[Pr + c] = A[r * MI + c];
    }
    __syncthreads();
    chol_body(sL, sD, sdi, tid);
    {
        int r = tid >> 2, sub = tid & 3;
        int Pr = (r * (r + 1)) >> 1;
        for (int c = sub; c <= r; c += 4) Lp[Pr + c] = sL[Pr + c];
    }
    if (tid < MI) dinv[tid] = sdi[tid];
}

// ============ column solve core ============
__device__ __forceinline__ void solve_core(const float* sLp, const float* sdi,
                                           const float* __restrict__ B, int ldb, int transB,
                                           float* __restrict__ X, int ldx,
                                           float scale, int col, int lane) {
    float x[8];
    int Pt[8];
    #pragma unroll
    for (int t = 0; t < 8; t++) {
        int j = lane + 32 * t;
        Pt[t] = (j * (j + 1)) >> 1;
        x[t] = transB ? B[col * ldb + j] : B[j * ldb + col];
    }
    #pragma unroll
    for (int s = 0; s < 8; s++) {
        #pragma unroll
        for (int mm = 0; mm < 32; mm++) {
            int m = s * 32 + mm;
            float xm = __shfl_sync(0xffffffffu, x[s], mm) * sdi[m];
            if (lane == mm) x[s] = xm;
            if (lane > mm)  x[s] -= xm * sLp[Pt[s] + m];
            #pragma unroll
            for (int t = s + 1; t < 8; t++)
                x[t] -= xm * sLp[Pt[t] + m];
        }
    }
    #pragma unroll
    for (int t = 0; t < 8; t++)
        X[(lane + 32 * t) * ldx + col] = x[t] * scale;
}

// solve1: Tmp = L^{-1} psi2 (transB, psi2 symmetric)
__global__ void __launch_bounds__(256) k_solve1(const float* __restrict__ Lp,
                                                const float* __restrict__ dinv) {
    extern __shared__ float sm[];
    float* sLp = sm;
    float* sdi = sm + PACKED;
    int tid = threadIdx.x, lane = tid & 31, wid = tid >> 5;
    for (int i = tid; i < PACKED; i += 256) sLp[i] = Lp[i];
    if (tid < MI) sdi[tid] = dinv[tid];
    __syncthreads();
    solve_core(sLp, sdi, g_psi2, MI, 1, g_tmp, MI, 1.0f, blockIdx.x * 8 + wid, lane);
}

// solve2: AAT = L^{-1} Tmp^T / sigma2
__global__ void __launch_bounds__(256) k_solve2(const float* __restrict__ Lp,
                                                const float* __restrict__ dinv) {
    extern __shared__ float sm[];
    float* sLp = sm;
    float* sdi = sm + PACKED;
    int tid = threadIdx.x, lane = tid & 31, wid = tid >> 5;
    for (int i = tid; i < PACKED; i += 256) sLp[i] = Lp[i];
    if (tid < MI) sdi[tid] = dinv[tid];
    __syncthreads();
    solve_core(sLp, sdi, g_tmp, MI, 1, g_AAT, MI, 1000.0f, blockIdx.x * 8 + wid, lane);
}

// solveH: H = L^{-1} G  (side stream)
__global__ void __launch_bounds__(256) k_solveH(const float* __restrict__ Lp,
                                                const float* __restrict__ dinv) {
    extern __shared__ float sm[];
    float* sLp = sm;
    float* sdi = sm + PACKED;
    int tid = threadIdx.x, lane = tid & 31, wid = tid >> 5;
    for (int i = tid; i < PACKED; i += 256) sLp[i] = Lp[i];
    if (tid < MI) sdi[tid] = dinv[tid];
    __syncthreads();
    int col = blockIdx.x * 8 + wid;
    if (col < DO)
        solve_core(sLp, sdi, g_G, DO, 0, g_H, DO, 1.0f, col, lane);
}

// ---------------- G = psi1^T @ Y  [MI x DO] ----------------
__global__ void k_gemm_G(const float* __restrict__ Y) {
    int m = blockIdx.x, tid = threadIdx.x;  // 128 threads
    float acc[DO] = {};
    for (int n = tid; n < NH; n += 128) {
        float a = g_psi1T[m * NH + n];
        const float4* y4 = (const float4*)&Y[n * DO];
        #pragma unroll
        for (int d4 = 0; d4 < 4; d4++) {
            float4 y = y4[d4];
            acc[4*d4 + 0] = fmaf(a, y.x, acc[4*d4 + 0]);
            acc[4*d4 + 1] = fmaf(a, y.y, acc[4*d4 + 1]);
            acc[4*d4 + 2] = fmaf(a, y.z, acc[4*d4 + 2]);
            acc[4*d4 + 3] = fmaf(a, y.w, acc[4*d4 + 3]);
        }
    }
    __shared__ float sred[128];
    for (int d = 0; d < DO; d++) {
        sred[tid] = acc[d];
        __syncthreads();
        for (int s = 64; s > 0; s >>= 1) {
            if (tid < s) sred[tid] += sred[tid + s];
            __syncthreads();
        }
        if (tid == 0) g_G[m * DO + d] = sred[0];
        __syncthreads();
    }
}

// ====== finish: chol(AAT+I) in SMEM, c = LB^{-1} H / sigma2, bound assembly ======
__global__ void __launch_bounds__(1024) k_finish(const float* __restrict__ Y,
                                                 const float* __restrict__ kvp,
                                                 float* __restrict__ out) {
    extern __shared__ float smf[];
    double* sred = (double*)smf;
    float* sL    = smf + 2048;
    float* sD    = sL + PACKED;
    float* sdi   = sD + 64*65;
    float* sdiag = sdi + 256;
    int tid = threadIdx.x, lane = tid & 31, wid = tid >> 5;

    {
        int r = tid >> 2, sub = tid & 3;
        int Pr = (r * (r + 1)) >> 1;
        for (int c = sub; c <= r; c += 4) {
            float v = g_AAT[r * MI + c];
            if (c == r) { sdiag[r] = v; v += 1.f; }
            sL[Pr + c] = v;
        }
    }
    __syncthreads();
    chol_body(sL, sD, sdi, tid);

    if (wid < DO) {
        float x[8];
        int Pt[8];
        #pragma unroll
        for (int t = 0; t < 8; t++) {
            int j = lane + 32 * t;
            Pt[t] = (j * (j + 1)) >> 1;
            x[t] = g_H[j * DO + wid];
        }
        #pragma unroll
        for (int s = 0; s < 8; s++) {
            #pragma unroll
            for (int mm = 0; mm < 32; mm++) {
                int m = s * 32 + mm;
                float xm = __shfl_sync(0xffffffffu, x[s], mm) * sdi[m];
                if (lane == mm) x[s] = xm;
                if (lane > mm)  x[s] -= xm * sL[Pt[s] + m];
                #pragma unroll
                for (int t = s + 1; t < 8; t++)
                    x[t] -= xm * sL[Pt[t] + m];
            }
        }
        #pragma unroll
        for (int t = 0; t < 8; t++)
            sD[(lane + 32 * t) * DO + wid] = x[t] * 1000.0f;
    }
    __syncthreads();

    double y2 = 0.0, c2 = 0.0, tr = 0.0, ld = 0.0;
    for (int i = tid; i < NH * DO; i += 1024) { double y = Y[i]; y2 = fma(y, y, y2); }
    for (int i = tid; i < MI * DO; i += 1024) { double v = sD[i]; c2 = fma(v, v, c2); }
    if (tid < MI) {
        tr = (double)sdiag[tid];
        ld = -log((double)sdi[tid]);
    }
    double vals[4] = { y2, c2, tr, ld };
    double res[4];
    for (int v = 0; v < 4; v++) {
        sred[tid] = vals[v];
        __syncthreads();
        for (int s = 512; s > 0; s >>= 1) {
            if (tid < s) sred[tid] += sred[tid + s];
            __syncthreads();
        }
        res[v] = sred[0];
        __syncthreads();
    }
    if (tid == 0) {
        double sigma2 = 1.0e-3;
        double kv = (double)(*kvp);
        double psi0 = (double)NH * kv;
        double bound = -0.5 * (double)NH * (double)DO * log(2.0 * M_PI * sigma2);
        bound -= 0.5 / sigma2 * res[0];
        bound -= 0.5 * (double)DO * (psi0 / sigma2 - res[2]);
        bound -= (double)DO * res[3];
        bound += 0.5 * res[1];
        out[0] = (float)bound;
    }
}

// ---------------- stream/event resources ----------------
struct StreamInit {
    cudaStream_t s2;
    cudaEvent_t evA, evP, evB;
    bool ok;
    StreamInit() : s2(nullptr), ok(false) {
        if (cudaStreamCreateWithFlags(&s2, cudaStreamNonBlocking) != cudaSuccess) return;
        if (cudaEventCreateWithFlags(&evA, cudaEventDisableTiming) != cudaSuccess) return;
        if (cudaEventCreateWithFlags(&evP, cudaEventDisableTiming) != cudaSuccess) return;
        if (cudaEventCreateWithFlags(&evB, cudaEventDisableTiming) != cudaSuccess) return;
        ok = true;
    }
};
static StreamInit g_si;

// ---------------- host launcher ----------------
extern "C" void kernel_launch(void* const* d_in, const int* in_sizes, int n_in,
                              void* d_out, int out_size) {
    const float* Xm = (const float*)d_in[0];
    const float* Xv = (const float*)d_in[1];
    const float* Z  = (const float*)d_in[2];
    const float* Y  = (const float*)d_in[3];
    const float* kv = (const float*)d_in[4];
    const float* ls = (const float*)d_in[5];
    float* out = (float*)d_out;

    float *pKuu, *pLp, *pDA;
    cudaGetSymbolAddress((void**)&pKuu, g_Kuu);
    cudaGetSymbolAddress((void**)&pLp,  g_Lp);
    cudaGetSymbolAddress((void**)&pDA,  g_dinvA);

    const int PSI2_SMEM   = (4 * DIN * 64 + 416) * (int)sizeof(float);  // 83,584
    const int CHOL_SMEM   = (PACKED + 64*65 + 256) * (int)sizeof(float);
    const int SOLVE_SMEM  = (PACKED + 256) * (int)sizeof(float);
    const int FINISH_SMEM = 2048 * (int)sizeof(float) + (PACKED + 64*65 + 256 + 256) * (int)sizeof(float);
    cudaFuncSetAttribute(k_psi2,    cudaFuncAttributeMaxDynamicSharedMemorySize, PSI2_SMEM);
    cudaFuncSetAttribute(k_chol256, cudaFuncAttributeMaxDynamicSharedMemorySize, CHOL_SMEM);
    cudaFuncSetAttribute(k_solve1,  cudaFuncAttributeMaxDynamicSharedMemorySize, SOLVE_SMEM);
    cudaFuncSetAttribute(k_solve2,  cudaFuncAttributeMaxDynamicSharedMemorySize, SOLVE_SMEM);
    cudaFuncSetAttribute(k_solveH,  cudaFuncAttributeMaxDynamicSharedMemorySize, SOLVE_SMEM);
    cudaFuncSetAttribute(k_finish,  cudaFuncAttributeMaxDynamicSharedMemorySize, FINISH_SMEM);

    if (g_si.ok) {
        cudaStream_t s2 = g_si.s2;
        cudaEventRecord(g_si.evA, 0);
        cudaStreamWaitEvent(s2, g_si.evA, 0);
        k_kuu<<<dim3(16, 16), dim3(16, 16), 0, s2>>>(Z, ls, kv);
        k_chol256<<<1, 1024, CHOL_SMEM, s2>>>(pKuu, pLp, pDA);

        k_prep<<<NH, 128>>>(Xm, Xv, ls);
        k_psi1F<<<dim3(4, 125), 256>>>(Z, kv);
        cudaEventRecord(g_si.evP, 0);
        cudaStreamWaitEvent(s2, g_si.evP, 0);
        k_gemm_G<<<MI, 128, 0, s2>>>(Y);
        k_solveH<<<2, 256, SOLVE_SMEM, s2>>>(pLp, pDA);
        cudaEventRecord(g_si.evB, s2);

        k_psi2<<<dim3(10, NCHUNK), 256, PSI2_SMEM>>>(Z);
        k_reduce_psi2<<<256, 256>>>();
        cudaStreamWaitEvent(0, g_si.evB, 0);
        k_solve1<<<32, 256, SOLVE_SMEM>>>(pLp, pDA);
        k_solve2<<<32, 256, SOLVE_SMEM>>>(pLp, pDA);
        k_finish<<<1, 1024, FINISH_SMEM>>>(Y, kv, out);
    } else {
        k_prep<<<NH, 128>>>(Xm, Xv, ls);
        k_kuu<<<dim3(16, 16), dim3(16, 16)>>>(Z, ls, kv);
        k_chol256<<<1, 1024, CHOL_SMEM>>>(pKuu, pLp, pDA);
        k_psi1F<<<dim3(4, 125), 256>>>(Z, kv);
        k_gemm_G<<<MI, 128>>>(Y);
        k_solveH<<<2, 256, SOLVE_SMEM>>>(pLp, pDA);
        k_psi2<<<dim3(10, NCHUNK), 256, PSI2_SMEM>>>(Z);
        k_reduce_psi2<<<256, 256>>>();
        k_solve1<<<32, 256, SOLVE_SMEM>>>(pLp, pDA);
        k_solve2<<<32, 256, SOLVE_SMEM>>>(pLp, pDA);
        k_finish<<<1, 1024, FINISH_SMEM>>>(Y, kv, out);
    }
}

// round 8
// speedup vs baseline: 1.2798x; 1.2798x over previous
#include <cuda_runtime.h>
#include <math.h>

#define NTOT 2010
#define QD 8
#define LTW 10
#define DIN 80
#define NH 2000
#define MI 256
#define DO 16
#define NCHUNK 44
#define CHUNK 46
#define JITTERF 1.0e-4f
#define PACKED 32896   // 256*257/2

// ---------------- device scratch (static, no allocation) ----------------
__device__ float g_P[NH*DIN], g_R[NH*DIN], g_U[NH*DIN], g_W[NH*DIN];
__device__ float g_a1[NH], g_lc1[NH], g_h[NH];
__device__ float g_F[NH*MI];
__device__ float g_psi1T[MI*NH];
__device__ float g_Kuu[MI*MI];
__device__ float g_pd[MI*MI];
__device__ float g_part[NCHUNK*MI*MI];
__device__ float g_Lp[PACKED];
__device__ float g_dinvA[MI];
__device__ float g_tmp[MI*MI];
__device__ float g_AAT[MI*MI];
__device__ float g_G[MI*DO];
__device__ float g_H[MI*DO];

__constant__ int c_ta[10] = {0,0,0,0,1,1,1,2,2,3};
__constant__ int c_tb[10] = {0,1,2,3,1,2,3,2,3,3};

// ---------------- per-n preprocessing ----------------
__global__ void k_prep(const float* __restrict__ Xm, const float* __restrict__ Xv,
                       const float* __restrict__ ls) {
    int n = blockIdx.x, t = threadIdx.x;
    float4 v = make_float4(0.f, 0.f, 0.f, 0.f);
    if (t < DIN) {
        int l = t / QD, q = t - l * QD;
        float xm = Xm[(1 + n + l) * QD + q];
        float xv = Xv[(1 + n + l) * QD + q];
        float lsv = ls[t];
        float ls2 = lsv * lsv;
        float d1 = xv + ls2, d2 = 2.f * xv + ls2;
        float id1 = 1.f / d1, id2 = 1.f / d2;
        g_P[n*DIN + t] = xm * id1;
        g_R[n*DIN + t] = id1;
        g_U[n*DIN + t] = xm * id2;
        g_W[n*DIN + t] = id2;
        v.x = xm * xm * id1;
        v.y = log1pf(xv / ls2);
        v.z = xm * xm * id2;
        v.w = log1pf(2.f * xv / ls2);
    }
    __shared__ float4 sr[128];
    sr[t] = v;
    __syncthreads();
    for (int s = 64; s > 0; s >>= 1) {
        if (t < s) {
            float4 a = sr[t], b = sr[t + s];
            a.x += b.x; a.y += b.y; a.z += b.z; a.w += b.w;
            sr[t] = a;
        }
        __syncthreads();
    }
    if (t == 0) {
        float4 r = sr[0];
        g_a1[n]  = r.x;
        g_lc1[n] = -0.5f * r.y;
        g_h[n]   = -0.5f * r.w - r.z;
    }
}

// ---------------- Kuu + kv^2*distfac ----------------
__global__ void k_kuu(const float* __restrict__ Z, const float* __restrict__ ls,
                      const float* __restrict__ kvp) {
    __shared__ float sZa[16][DIN+1], sZb[16][DIN+1], sil[DIN];
    int a0 = blockIdx.y * 16, b0 = blockIdx.x * 16;
    int tx = threadIdx.x, ty = threadIdx.y, tid = ty * 16 + tx;
    for (int i = tid; i < 16 * DIN; i += 256) {
        int r = i / DIN, q = i - r * DIN;
        sZa[r][q] = Z[(a0 + r) * DIN + q];
        sZb[r][q] = Z[(b0 + r) * DIN + q];
    }
    if (tid < DIN) { float L = ls[tid]; sil[tid] = 1.f / (L * L); }
    __syncthreads();
    float d2 = 0.f;
    #pragma unroll 16
    for (int q = 0; q < DIN; q++) {
        float d = sZa[ty][q] - sZb[tx][q];
        d2 = fmaf(d * d, sil[q], d2);
    }
    float kv = *kvp;
    int a = a0 + ty, b = b0 + tx;
    g_Kuu[a*MI + b] = kv * __expf(-0.5f * d2) + ((a == b) ? JITTERF : 0.f);
    g_pd[a*MI + b]  = kv * kv * __expf(-0.25f * d2);
}

// ---------------- psi1^T and F : 16n x 64m tiles ----------------
__global__ void __launch_bounds__(256) k_psi1F(const float* __restrict__ Z,
                                               const float* __restrict__ kvp) {
    __shared__ float sZm[DIN*64];        // [q][m]
    __shared__ float4 sS4[16*DIN];       // (P,R,U,W) per [n][q]
    int m0 = blockIdx.x * 64, n0 = blockIdx.y * 16;
    int tid = threadIdx.x;
    int mg = tid & 15, ny = tid >> 4;
    for (int i = tid; i < 64 * DIN; i += 256) {
        int r = i & 63, q = i >> 6;
        sZm[q*64 + r] = Z[(m0 + r) * DIN + q];
    }
    for (int i = tid; i < 16 * DIN; i += 256) {
        int r = i / DIN, q = i - r * DIN;
        int ni = (n0 + r) * DIN + q;
        sS4[i] = make_float4(g_P[ni], g_R[ni], g_U[ni], g_W[ni]);
    }
    __syncthreads();
    float pz[4] = {}, rz[4] = {}, uz[4] = {}, wz[4] = {};
    #pragma unroll 5
    for (int q = 0; q < DIN; q++) {
        float4 z4 = *(const float4*)&sZm[q*64 + mg*4];
        float4 pw = sS4[ny*DIN + q];
        float z, zq;
        z = z4.x; zq = z*z;
        pz[0] = fmaf(pw.x, z, pz[0]); rz[0] = fmaf(pw.y, zq, rz[0]);
        uz[0] = fmaf(pw.z, z, uz[0]); wz[0] = fmaf(pw.w, zq, wz[0]);
        z = z4.y; zq = z*z;
        pz[1] = fmaf(pw.x, z, pz[1]); rz[1] = fmaf(pw.y, zq, rz[1]);
        uz[1] = fmaf(pw.z, z, uz[1]); wz[1] = fmaf(pw.w, zq, wz[1]);
        z = z4.z; zq = z*z;
        pz[2] = fmaf(pw.x, z, pz[2]); rz[2] = fmaf(pw.y, zq, rz[2]);
        uz[2] = fmaf(pw.z, z, uz[2]); wz[2] = fmaf(pw.w, zq, wz[2]);
        z = z4.w; zq = z*z;
        pz[3] = fmaf(pw.x, z, pz[3]); rz[3] = fmaf(pw.y, zq, rz[3]);
        uz[3] = fmaf(pw.z, z, uz[3]); wz[3] = fmaf(pw.w, zq, wz[3]);
    }
    int n = n0 + ny;
    float a1 = g_a1[n], lc1 = g_lc1[n], h = g_h[n];
    float kv = *kvp;
    #pragma unroll
    for (int k = 0; k < 4; k++) {
        int m = m0 + mg * 4 + k;
        g_psi1T[m*NH + n] = kv * __expf(fmaf(-0.5f, a1 - 2.f * pz[k] + rz[k], lc1));
        g_F[n*MI + m]     = __expf(0.5f * h + uz[k] - 0.25f * wz[k]);
    }
}

// ---------------- big psi2 kernel (proven R4/R5 scalar, dyn smem) ----------------
__global__ void __launch_bounds__(256) k_psi2(const float* __restrict__ Z) {
    extern __shared__ float dsm[];
    float* sZa = dsm;
    float* sZb = sZa + DIN*64;
    float* sWZ = sZb + DIN*64;
    float* sW  = sWZ + DIN*64;
    float* sFa = sW + DIN;
    float* sFb = sFa + 64;
    int tp = blockIdx.x, ch = blockIdx.y;
    int a0 = c_ta[tp] * 64, b0 = c_tb[tp] * 64;
    int tid = threadIdx.x;
    for (int i = tid; i < 64 * DIN; i += 256) {
        int r = i & 63, q = i >> 6;
        sZa[q*64 + r] = Z[(a0 + r) * DIN + q];
        sZb[q*64 + r] = Z[(b0 + r) * DIN + q];
    }
    int tx = tid & 15, ty = tid >> 4;
    float acc[4][4] = {};
    int n0 = ch * CHUNK;
    int n1 = n0 + CHUNK; if (n1 > NH) n1 = NH;
    for (int n = n0; n < n1; n++) {
        __syncthreads();
        if (tid < DIN)                      sW[tid]        = g_W[n*DIN + tid];
        else if (tid >= 128 && tid < 192)   sFa[tid - 128] = g_F[n*MI + a0 + (tid - 128)];
        else if (tid >= 192)                sFb[tid - 192] = g_F[n*MI + b0 + (tid - 192)];
        __syncthreads();
        for (int i = tid; i < 64 * DIN; i += 256)
            sWZ[i] = -0.5f * sW[i >> 6] * sZa[i];
        __syncthreads();
        float C[4][4] = {};
        #pragma unroll 10
        for (int q = 0; q < DIN; q++) {
            float4 wa = *(const float4*)&sWZ[q*64 + tx*4];
            float4 zb = *(const float4*)&sZb[q*64 + ty*4];
            C[0][0] = fmaf(wa.x, zb.x, C[0][0]); C[0][1] = fmaf(wa.x, zb.y, C[0][1]);
            C[0][2] = fmaf(wa.x, zb.z, C[0][2]); C[0][3] = fmaf(wa.x, zb.w, C[0][3]);
            C[1][0] = fmaf(wa.y, zb.x, C[1][0]); C[1][1] = fmaf(wa.y, zb.y, C[1][1]);
            C[1][2] = fmaf(wa.y, zb.z, C[1][2]); C[1][3] = fmaf(wa.y, zb.w, C[1][3]);
            C[2][0] = fmaf(wa.z, zb.x, C[2][0]); C[2][1] = fmaf(wa.z, zb.y, C[2][1]);
            C[2][2] = fmaf(wa.z, zb.z, C[2][2]); C[2][3] = fmaf(wa.z, zb.w, C[2][3]);
            C[3][0] = fmaf(wa.w, zb.x, C[3][0]); C[3][1] = fmaf(wa.w, zb.y, C[3][1]);
            C[3][2] = fmaf(wa.w, zb.z, C[3][2]); C[3][3] = fmaf(wa.w, zb.w, C[3][3]);
        }
        float fa[4], fb[4];
        #pragma unroll
        for (int i = 0; i < 4; i++) { fa[i] = sFa[tx*4 + i]; fb[i] = sFb[ty*4 + i]; }
        #pragma unroll
        for (int i = 0; i < 4; i++)
            #pragma unroll
            for (int j = 0; j < 4; j++)
                acc[i][j] = fmaf(fa[i] * fb[j], __expf(C[i][j]), acc[i][j]);
    }
    float* part = &g_part[(size_t)ch * MI * MI];
    #pragma unroll
    for (int i = 0; i < 4; i++) {
        int a = a0 + tx * 4 + i;
        #pragma unroll
        for (int j = 0; j < 4; j++) {
            int b = b0 + ty * 4 + j;
            part[a*MI + b] = acc[i][j];
        }
    }
}

// ============ Cholesky body: all-thread elimination diag + ILP panel + SYRK ======
__device__ __forceinline__ void chol_body(float* sL, float* sD, float* sdi, int tid) {
    int lane = tid & 31, wid = tid >> 5;
    for (int K = 0; K < 4; K++) {
        int base = K * 64;
        // load diag block (lower incl diag)
        for (int i = tid; i < 64 * 64; i += 1024) {
            int r = i >> 6, c = i & 63;
            if (c <= r) sD[r*65 + c] = sL[(((base+r)*(base+r+1))>>1) + base + c];
        }
        __syncthreads();
        // right-looking elimination (scaling deferred); 1 sync per step
        {
            int myc = tid & 63;
            int rbase = tid >> 6;
            for (int k = 0; k < 64; k++) {
                float piv = sD[k*65 + k];
                float si = 1.f / sqrtf(piv);
                float inv2 = 1.f / piv;
                if (tid == 0) sdi[base + k] = si;
                float ljk = (myc > k) ? sD[myc*65 + k] * inv2 : 0.f;
                #pragma unroll
                for (int s = 0; s < 4; s++) {
                    int r = rbase + s * 16;
                    if (r > k && myc > k && myc <= r)
                        sD[r*65 + myc] -= sD[r*65 + k] * ljk;
                }
                __syncthreads();
            }
        }
        // final scale + write-back to packed
        for (int i = tid; i < 64 * 64; i += 1024) {
            int r = i >> 6, c = i & 63;
            if (c <= r) {
                float v = sD[r*65 + c] * sdi[base + c];
                sD[r*65 + c] = v;
                sL[(((base+r)*(base+r+1))>>1) + base + c] = v;
            }
        }
        __syncthreads();
        int R = MI - base - 64;
        if (R > 0) {
            // panel: 2 rows per warp (ILP), shuffle substitution vs sD
            for (int rr = wid; rr < R; rr += 64) {
                int rowA = base + 64 + rr;
                int rowB = rowA + 32;
                int PrA = (rowA * (rowA + 1)) >> 1;
                int PrB = (rowB * (rowB + 1)) >> 1;
                float x0 = sL[PrA + base + lane];
                float x1 = sL[PrA + base + 32 + lane];
                float y0 = sL[PrB + base + lane];
                float y1 = sL[PrB + base + 32 + lane];
                #pragma unroll
                for (int m = 0; m < 64; m++) {
                    float va = __shfl_sync(0xffffffffu, (m < 32) ? x0 : x1, m & 31);
                    float vb = __shfl_sync(0xffffffffu, (m < 32) ? y0 : y1, m & 31);
                    float inv = sdi[base + m];
                    float xa = va * inv, xb = vb * inv;
                    if (m < 32) {
                        float l0 = sD[lane*65 + m];
                        float l1 = sD[(lane+32)*65 + m];
                        if (lane == m) { x0 = xa; y0 = xb; }
                        if (lane > m)  { x0 -= xa * l0; y0 -= xb * l0; }
                        x1 -= xa * l1; y1 -= xb * l1;
                    } else {
                        float l1 = sD[(lane+32)*65 + m];
                        if (lane == m - 32) { x1 = xa; y1 = xb; }
                        if (lane + 32 > m)  { x1 -= xa * l1; y1 -= xb * l1; }
                    }
                }
                sL[PrA + base + lane]      = x0;
                sL[PrA + base + 32 + lane] = x1;
                sL[PrB + base + lane]      = y0;
                sL[PrB + base + 32 + lane] = y1;
            }
            __syncthreads();
            // trailing SYRK: 32x32 tiles, 64 threads/tile, 4x4 micro
            int T = R >> 5;
            int ntiles = (T * (T + 1)) >> 1;
            int g = tid >> 6, gt = tid & 63;
            int txx = gt & 7, tyy = gt >> 3;
            for (int tile = g; tile < ntiles; tile += 16) {
                int ti = 0, rem = tile;
                while (rem > ti) { rem -= (ti + 1); ti++; }
                int tj = rem;
                int gr = base + 64 + ti * 32, gc = base + 64 + tj * 32;
                int Pr[4], Pc[4];
                #pragma unroll
                for (int i = 0; i < 4; i++) { int r = gr + tyy*4 + i; Pr[i] = ((r*(r+1))>>1) + base; }
                #pragma unroll
                for (int j = 0; j < 4; j++) { int c = gc + txx*4 + j; Pc[j] = ((c*(c+1))>>1) + base; }
                float acc[4][4] = {};
                #pragma unroll 16
                for (int k = 0; k < 64; k++) {
                    float la[4], lb[4];
                    #pragma unroll
                    for (int i = 0; i < 4; i++) la[i] = sL[Pr[i] + k];
                    #pragma unroll
                    for (int j = 0; j < 4; j++) lb[j] = sL[Pc[j] + k];
                    #pragma unroll
                    for (int i = 0; i < 4; i++)
                        #pragma unroll
                        for (int j = 0; j < 4; j++)
                            acc[i][j] = fmaf(la[i], lb[j], acc[i][j]);
                }
                #pragma unroll
                for (int i = 0; i < 4; i++) {
                    int r = gr + tyy*4 + i;
                    int Prow = (r * (r + 1)) >> 1;
                    #pragma unroll
                    for (int j = 0; j < 4; j++) {
                        int c = gc + txx*4 + j;
                        if (c <= r) sL[Prow + c] -= acc[i][j];
                    }
                }
            }
        }
        __syncthreads();
    }
}

// chol(Kuu) -> packed L in global + dinv
__global__ void __launch_bounds__(1024) k_chol256(const float* __restrict__ A,
                                                  float* __restrict__ Lp,
                                                  float* __restrict__ dinv) {
    extern __shared__ float sm[];
    float* sL  = sm;
    float* sD  = sm + PACKED;
    float* sdi = sD + 64*65;
    int tid = threadIdx.x;
    {
        int r = tid >> 2, sub = tid & 3;
        int Pr = (r * (r + 1)) >> 1;
        for (int c = sub; c <= r; c += 4) sL[Pr + c] = A[r * MI + c];
    }
    __syncthreads();
    chol_body(sL, sD, sdi, tid);
    {
        int r = tid >> 2, sub = tid & 3;
        int Pr = (r * (r + 1)) >> 1;
        for (int c = sub; c <= r; c += 4) Lp[Pr + c] = sL[Pr + c];
    }
    if (tid < MI) dinv[tid] = sdi[tid];
}

// ============ column solve recurrence + store ============
__device__ __forceinline__ void solve_rec_store(const float* sLp, const float* sdi,
                                                float x[8], const int Pt[8],
                                                float* __restrict__ X, int ldx,
                                                float scale, int col, int lane) {
    #pragma unroll
    for (int s = 0; s < 8; s++) {
        #pragma unroll
        for (int mm = 0; mm < 32; mm++) {
            int m = s * 32 + mm;
            float xm = __shfl_sync(0xffffffffu, x[s], mm) * sdi[m];
            if (lane == mm) x[s] = xm;
            if (lane > mm)  x[s] -= xm * sLp[Pt[s] + m];
            #pragma unroll
            for (int t = s + 1; t < 8; t++)
                x[t] -= xm * sLp[Pt[t] + m];
        }
    }
    #pragma unroll
    for (int t = 0; t < 8; t++)
        X[(lane + 32 * t) * ldx + col] = x[t] * scale;
}

// solve1: Tmp = L^{-1} psi2, with psi2 built on the fly from g_part + g_pd
__global__ void __launch_bounds__(256) k_solve1(const float* __restrict__ Lp,
                                                const float* __restrict__ dinv) {
    extern __shared__ float sm[];
    float* sLp = sm;
    float* sdi = sm + PACKED;
    int tid = threadIdx.x, lane = tid & 31, wid = tid >> 5;
    for (int i = tid; i < PACKED; i += 256) sLp[i] = Lp[i];
    if (tid < MI) sdi[tid] = dinv[tid];
    int col = blockIdx.x * 8 + wid;
    float x[8];
    int Pt[8];
    int colT = col >> 6;
    #pragma unroll
    for (int t = 0; t < 8; t++) {
        int j = lane + 32 * t;
        Pt[t] = (j * (j + 1)) >> 1;
        int jT = j >> 6;
        int idx = (colT <= jT) ? (col * MI + j) : (j * MI + col);
        float s = 0.f;
        #pragma unroll
        for (int ch = 0; ch < NCHUNK; ch++) s += g_part[ch * MI * MI + idx];
        x[t] = g_pd[col * MI + j] * s;
    }
    __syncthreads();
    solve_rec_store(sLp, sdi, x, Pt, g_tmp, MI, 1.0f, col, lane);
}

// solve2: AAT = L^{-1} Tmp^T / sigma2
__global__ void __launch_bounds__(256) k_solve2(const float* __restrict__ Lp,
                                                const float* __restrict__ dinv) {
    extern __shared__ float sm[];
    float* sLp = sm;
    float* sdi = sm + PACKED;
    int tid = threadIdx.x, lane = tid & 31, wid = tid >> 5;
    for (int i = tid; i < PACKED; i += 256) sLp[i] = Lp[i];
    if (tid < MI) sdi[tid] = dinv[tid];
    int col = blockIdx.x * 8 + wid;
    float x[8];
    int Pt[8];
    #pragma unroll
    for (int t = 0; t < 8; t++) {
        int j = lane + 32 * t;
        Pt[t] = (j * (j + 1)) >> 1;
        x[t] = g_tmp[col * MI + j];   // transB read
    }
    __syncthreads();
    solve_rec_store(sLp, sdi, x, Pt, g_AAT, MI, 1000.0f, col, lane);
}

// solveH: H = L^{-1} G  (side stream)
__global__ void __launch_bounds__(256) k_solveH(const float* __restrict__ Lp,
                                                const float* __restrict__ dinv) {
    extern __shared__ float sm[];
    float* sLp = sm;
    float* sdi = sm + PACKED;
    int tid = threadIdx.x, lane = tid & 31, wid = tid >> 5;
    for (int i = tid; i < PACKED; i += 256) sLp[i] = Lp[i];
    if (tid < MI) sdi[tid] = dinv[tid];
    int col = blockIdx.x * 8 + wid;
    float x[8];
    int Pt[8];
    #pragma unroll
    for (int t = 0; t < 8; t++) {
        int j = lane + 32 * t;
        Pt[t] = (j * (j + 1)) >> 1;
        x[t] = (col < DO) ? g_G[j * DO + col] : 0.f;
    }
    __syncthreads();
    if (col < DO)
        solve_rec_store(sLp, sdi, x, Pt, g_H, DO, 1.0f, col, lane);
}

// ---------------- G = psi1^T @ Y  [MI x DO] ----------------
__global__ void k_gemm_G(const float* __restrict__ Y) {
    int m = blockIdx.x, tid = threadIdx.x;  // 128 threads
    float acc[DO] = {};
    for (int n = tid; n < NH; n += 128) {
        float a = g_psi1T[m * NH + n];
        const float4* y4 = (const float4*)&Y[n * DO];
        #pragma unroll
        for (int d4 = 0; d4 < 4; d4++) {
            float4 y = y4[d4];
            acc[4*d4 + 0] = fmaf(a, y.x, acc[4*d4 + 0]);
            acc[4*d4 + 1] = fmaf(a, y.y, acc[4*d4 + 1]);
            acc[4*d4 + 2] = fmaf(a, y.z, acc[4*d4 + 2]);
            acc[4*d4 + 3] = fmaf(a, y.w, acc[4*d4 + 3]);
        }
    }
    __shared__ float sred[128];
    for (int d = 0; d < DO; d++) {
        sred[tid] = acc[d];
        __syncthreads();
        for (int s = 64; s > 0; s >>= 1) {
            if (tid < s) sred[tid] += sred[tid + s];
            __syncthreads();
        }
        if (tid == 0) g_G[m * DO + d] = sred[0];
        __syncthreads();
    }
}

// ====== finish: chol(AAT+I) in SMEM, c = LB^{-1} H / sigma2, bound assembly ======
__global__ void __launch_bounds__(1024) k_finish(const float* __restrict__ Y,
                                                 const float* __restrict__ kvp,
                                                 float* __restrict__ out) {
    extern __shared__ float smf[];
    double* sred = (double*)smf;
    float* sL    = smf + 2048;
    float* sD    = sL + PACKED;
    float* sdi   = sD + 64*65;
    float* sdiag = sdi + 256;
    int tid = threadIdx.x, lane = tid & 31, wid = tid >> 5;

    {
        int r = tid >> 2, sub = tid & 3;
        int Pr = (r * (r + 1)) >> 1;
        for (int c = sub; c <= r; c += 4) {
            float v = g_AAT[r * MI + c];
            if (c == r) { sdiag[r] = v; v += 1.f; }
            sL[Pr + c] = v;
        }
    }
    __syncthreads();
    chol_body(sL, sD, sdi, tid);

    if (wid < DO) {
        float x[8];
        int Pt[8];
        #pragma unroll
        for (int t = 0; t < 8; t++) {
            int j = lane + 32 * t;
            Pt[t] = (j * (j + 1)) >> 1;
            x[t] = g_H[j * DO + wid];
        }
        #pragma unroll
        for (int s = 0; s < 8; s++) {
            #pragma unroll
            for (int mm = 0; mm < 32; mm++) {
                int m = s * 32 + mm;
                float xm = __shfl_sync(0xffffffffu, x[s], mm) * sdi[m];
                if (lane == mm) x[s] = xm;
                if (lane > mm)  x[s] -= xm * sL[Pt[s] + m];
                #pragma unroll
                for (int t = s + 1; t < 8; t++)
                    x[t] -= xm * sL[Pt[t] + m];
            }
        }
        #pragma unroll
        for (int t = 0; t < 8; t++)
            sD[(lane + 32 * t) * DO + wid] = x[t] * 1000.0f;
    }
    __syncthreads();

    double y2 = 0.0, c2 = 0.0, tr = 0.0, ld = 0.0;
    for (int i = tid; i < NH * DO; i += 1024) { double y = Y[i]; y2 = fma(y, y, y2); }
    for (int i = tid; i < MI * DO; i += 1024) { double v = sD[i]; c2 = fma(v, v, c2); }
    if (tid < MI) {
        tr = (double)sdiag[tid];
        ld = -log((double)sdi[tid]);
    }
    double vals[4] = { y2, c2, tr, ld };
    double res[4];
    for (int v = 0; v < 4; v++) {
        sred[tid] = vals[v];
        __syncthreads();
        for (int s = 512; s > 0; s >>= 1) {
            if (tid < s) sred[tid] += sred[tid + s];
            __syncthreads();
        }
        res[v] = sred[0];
        __syncthreads();
    }
    if (tid == 0) {
        double sigma2 = 1.0e-3;
        double kv = (double)(*kvp);
        double psi0 = (double)NH * kv;
        double bound = -0.5 * (double)NH * (double)DO * log(2.0 * M_PI * sigma2);
        bound -= 0.5 / sigma2 * res[0];
        bound -= 0.5 * (double)DO * (psi0 / sigma2 - res[2]);
        bound -= (double)DO * res[3];
        bound += 0.5 * res[1];
        out[0] = (float)bound;
    }
}

// ---------------- stream/event resources ----------------
struct StreamInit {
    cudaStream_t s2;
    cudaEvent_t evA, evP, evB;
    bool ok;
    StreamInit() : s2(nullptr), ok(false) {
        if (cudaStreamCreateWithFlags(&s2, cudaStreamNonBlocking) != cudaSuccess) return;
        if (cudaEventCreateWithFlags(&evA, cudaEventDisableTiming) != cudaSuccess) return;
        if (cudaEventCreateWithFlags(&evP, cudaEventDisableTiming) != cudaSuccess) return;
        if (cudaEventCreateWithFlags(&evB, cudaEventDisableTiming) != cudaSuccess) return;
        ok = true;
    }
};
static StreamInit g_si;

// ---------------- host launcher ----------------
extern "C" void kernel_launch(void* const* d_in, const int* in_sizes, int n_in,
                              void* d_out, int out_size) {
    const float* Xm = (const float*)d_in[0];
    const float* Xv = (const float*)d_in[1];
    const float* Z  = (const float*)d_in[2];
    const float* Y  = (const float*)d_in[3];
    const float* kv = (const float*)d_in[4];
    const float* ls = (const float*)d_in[5];
    float* out = (float*)d_out;

    float *pKuu, *pLp, *pDA;
    cudaGetSymbolAddress((void**)&pKuu, g_Kuu);
    cudaGetSymbolAddress((void**)&pLp,  g_Lp);
    cudaGetSymbolAddress((void**)&pDA,  g_dinvA);

    const int PSI2_SMEM   = (3 * DIN * 64 + DIN + 128) * (int)sizeof(float);
    const int CHOL_SMEM   = (PACKED + 64*65 + 256) * (int)sizeof(float);
    const int SOLVE_SMEM  = (PACKED + 256) * (int)sizeof(float);
    const int FINISH_SMEM = 2048 * (int)sizeof(float) + (PACKED + 64*65 + 256 + 256) * (int)sizeof(float);
    cudaFuncSetAttribute(k_psi2,    cudaFuncAttributeMaxDynamicSharedMemorySize, PSI2_SMEM);
    cudaFuncSetAttribute(k_chol256, cudaFuncAttributeMaxDynamicSharedMemorySize, CHOL_SMEM);
    cudaFuncSetAttribute(k_solve1,  cudaFuncAttributeMaxDynamicSharedMemorySize, SOLVE_SMEM);
    cudaFuncSetAttribute(k_solve2,  cudaFuncAttributeMaxDynamicSharedMemorySize, SOLVE_SMEM);
    cudaFuncSetAttribute(k_solveH,  cudaFuncAttributeMaxDynamicSharedMemorySize, SOLVE_SMEM);
    cudaFuncSetAttribute(k_finish,  cudaFuncAttributeMaxDynamicSharedMemorySize, FINISH_SMEM);

    if (g_si.ok) {
        cudaStream_t s2 = g_si.s2;
        cudaEventRecord(g_si.evA, 0);
        cudaStreamWaitEvent(s2, g_si.evA, 0);
        k_kuu<<<dim3(16, 16), dim3(16, 16), 0, s2>>>(Z, ls, kv);
        k_chol256<<<1, 1024, CHOL_SMEM, s2>>>(pKuu, pLp, pDA);

        k_prep<<<NH, 128>>>(Xm, Xv, ls);
        k_psi1F<<<dim3(4, 125), 256>>>(Z, kv);
        cudaEventRecord(g_si.evP, 0);
        cudaStreamWaitEvent(s2, g_si.evP, 0);
        k_gemm_G<<<MI, 128, 0, s2>>>(Y);
        k_solveH<<<2, 256, SOLVE_SMEM, s2>>>(pLp, pDA);
        cudaEventRecord(g_si.evB, s2);

        k_psi2<<<dim3(10, NCHUNK), 256, PSI2_SMEM>>>(Z);
        cudaStreamWaitEvent(0, g_si.evB, 0);
        k_solve1<<<32, 256, SOLVE_SMEM>>>(pLp, pDA);
        k_solve2<<<32, 256, SOLVE_SMEM>>>(pLp, pDA);
        k_finish<<<1, 1024, FINISH_SMEM>>>(Y, kv, out);
    } else {
        k_prep<<<NH, 128>>>(Xm, Xv, ls);
        k_kuu<<<dim3(16, 16), dim3(16, 16)>>>(Z, ls, kv);
        k_chol256<<<1, 1024, CHOL_SMEM>>>(pKuu, pLp, pDA);
        k_psi1F<<<dim3(4, 125), 256>>>(Z, kv);
        k_gemm_G<<<MI, 128>>>(Y);
        k_solveH<<<2, 256, SOLVE_SMEM>>>(pLp, pDA);
        k_psi2<<<dim3(10, NCHUNK), 256, PSI2_SMEM>>>(Z);
        k_solve1<<<32, 256, SOLVE_SMEM>>>(pLp, pDA);
        k_solve2<<<32, 256, SOLVE_SMEM>>>(pLp, pDA);
        k_finish<<<1, 1024, FINISH_SMEM>>>(Y, kv, out);
    }
}